// round 15
// baseline (speedup 1.0000x reference)
#include <cuda_runtime.h>
#include <cuda_fp16.h>
#include <math.h>

#define NN 50000
#define EE 1600000
#define HID 64
#define NC 32
#define NFEAT 128
#define NG 4           // k-groups (64/16)
#define GK 16          // k-cols per group
#define GW 512         // values per X row = GK*NC (fp8 bytes)
#define CSTF 1e-5f
#define FULL 0xffffffffu
#define NBLK ((NN + 255) / 256)

// ---------------- scratch (device globals; no allocation allowed) ----------
__device__ int    g_deg[NN];
__device__ float  g_dinv[NN];
__device__ int    g_cptr[NN + 1];
__device__ int    g_cnt[NN];
__device__ float2 g_swp[EE];      // packed (src-as-float-bits, wgt)
__device__ int    g_bsum[NBLK];
__device__ int    g_boff[NBLK];
__device__ float  g_x[NN * HID];
__device__ float  g_Q[NN * HID];
__device__ float  g_Kf[NN * HID];
__device__ float  g_V[NN * NC];
__device__ __half g_Kh[NN * HID];
__device__ __half g_Vh[NN * NC];
__device__ __half g_Kha[NN * HID];
__device__ __half g_Khb[NN * HID];
__device__ float  g_coef[4 * NN];
__device__ float  g_tM[HID * NC];
__device__ float  g_tK[HID];
// fp8 (e4m3) X buffers: row = 32 uint4 (512 B) per node + per-row scale
__device__ uint4  g_X8a[NN * 32];   // 25.6 MB
__device__ uint4  g_X8b[NN * 32];   // 25.6 MB
__device__ float  g_sA[NN];
__device__ float  g_sB[NN];

// ---------------- setup kernels --------------------------------------------
__global__ void k_zero() {
    int i = blockIdx.x * blockDim.x + threadIdx.x;
    if (i < NN) { g_deg[i] = 0; g_cnt[i] = 0; }
    if (i < HID * NC) g_tM[i] = 0.f;
    if (i < HID) g_tK[i] = 0.f;
}

__global__ void k_hist(const int* __restrict__ col) {
    int e = blockIdx.x * blockDim.x + threadIdx.x;
    if (e < EE) atomicAdd(&g_deg[col[e]], 1);
}

__global__ void k_dinv() {
    int i = blockIdx.x * blockDim.x + threadIdx.x;
    if (i < NN) {
        int d = g_deg[i];
        g_dinv[i] = (d > 0) ? 1.0f / (float)d : 0.0f;
    }
}

__global__ void k_blksum() {
    __shared__ int sm[256];
    int b = blockIdx.x, t = threadIdx.x;
    int i = b * 256 + t;
    sm[t] = (i < NN) ? g_deg[i] : 0;
    __syncthreads();
    for (int o = 128; o > 0; o >>= 1) {
        if (t < o) sm[t] += sm[t + o];
        __syncthreads();
    }
    if (t == 0) g_bsum[b] = sm[0];
}

__global__ void k_scanblk() {
    __shared__ int sm[256];
    int t = threadIdx.x;
    int v = (t < NBLK) ? g_bsum[t] : 0;
    sm[t] = v;
    __syncthreads();
    for (int o = 1; o < 256; o <<= 1) {
        int u = 0;
        if (t >= o) u = sm[t - o];
        __syncthreads();
        sm[t] += u;
        __syncthreads();
    }
    if (t < NBLK) g_boff[t] = sm[t] - v;
}

__global__ void k_cptr() {
    __shared__ int sm[256];
    int b = blockIdx.x, t = threadIdx.x;
    int i = b * 256 + t;
    int v = (i < NN) ? g_deg[i] : 0;
    sm[t] = v;
    __syncthreads();
    for (int o = 1; o < 256; o <<= 1) {
        int u = 0;
        if (t >= o) u = sm[t - o];
        __syncthreads();
        sm[t] += u;
        __syncthreads();
    }
    int incl = sm[t];
    if (i < NN) g_cptr[i] = g_boff[b] + incl - v;
    if (i == NN - 1) g_cptr[NN] = g_boff[b] + incl;
}

__global__ void k_scatter(const int* __restrict__ row, const int* __restrict__ col) {
    int e = blockIdx.x * blockDim.x + threadIdx.x;
    if (e < EE) {
        int c = col[e];
        int r = row[e];
        int pos = g_cptr[c] + atomicAdd(&g_cnt[c], 1);
        g_swp[pos] = make_float2(__int_as_float(r), g_dinv[r]);
    }
}

// ---------------- input GEMMs ----------------------------------------------
__global__ void k_gemmA(const float* __restrict__ nf, const float* __restrict__ W,
                        const float* __restrict__ b) {
    __shared__ __align__(16) float Ws[NFEAT * HID];
    __shared__ __align__(16) float xs[16 * NFEAT];
    __shared__ __align__(16) float bs[HID];
    int tid = threadIdx.y * 16 + threadIdx.x;
    for (int i = tid; i < NFEAT * HID; i += 256) Ws[i] = W[i];
    if (tid < HID) bs[tid] = b[tid];
    int nb = blockIdx.x * 16;
    for (int i = tid; i < 16 * NFEAT; i += 256) {
        int n = i >> 7, f = i & 127;
        xs[i] = nf[(nb + n) * NFEAT + f];
    }
    __syncthreads();
    int node = nb + threadIdx.y;
    int oq = threadIdx.x;
    float4 acc = *(const float4*)&bs[oq * 4];
    const float* xr = &xs[threadIdx.y * NFEAT];
#pragma unroll 8
    for (int f = 0; f < NFEAT; f++) {
        float v = xr[f];
        float4 w = *(const float4*)&Ws[f * HID + oq * 4];
        acc.x += v * w.x; acc.y += v * w.y; acc.z += v * w.z; acc.w += v * w.w;
    }
    acc.x = fmaxf(acc.x, 0.f); acc.y = fmaxf(acc.y, 0.f);
    acc.z = fmaxf(acc.z, 0.f); acc.w = fmaxf(acc.w, 0.f);
    *(float4*)&g_x[node * HID + oq * 4] = acc;
}

__global__ void k_gemmB(const float* __restrict__ WQ, const float* __restrict__ bQ,
                        const float* __restrict__ WK, const float* __restrict__ bK,
                        const float* __restrict__ WV, const float* __restrict__ bV) {
    __shared__ __align__(16) float Wc[HID * 160];
    __shared__ __align__(16) float xs[8 * HID];
    __shared__ __align__(16) float bc[160];
    int tid = threadIdx.y * 40 + threadIdx.x;  // 320 threads
    for (int i = tid; i < HID * 160; i += 320) {
        int f = i / 160, o = i % 160;
        float v;
        if (o < 64) v = WQ[f * 64 + o];
        else if (o < 128) v = WK[f * 64 + (o - 64)];
        else v = WV[f * 32 + (o - 128)];
        Wc[i] = v;
    }
    if (tid < 160)
        bc[tid] = (tid < 64) ? bQ[tid] : ((tid < 128) ? bK[tid - 64] : bV[tid - 128]);
    int nb = blockIdx.x * 8;
    for (int i = tid; i < 8 * HID; i += 320) {
        int n = i >> 6, f = i & 63;
        xs[i] = g_x[(nb + n) * HID + f];
    }
    __syncthreads();
    int node = nb + threadIdx.y;
    int oq = threadIdx.x;
    float4 acc = *(const float4*)&bc[oq * 4];
    const float* xr = &xs[threadIdx.y * HID];
#pragma unroll 8
    for (int f = 0; f < HID; f++) {
        float v = xr[f];
        float4 w = *(const float4*)&Wc[f * 160 + oq * 4];
        acc.x += v * w.x; acc.y += v * w.y; acc.z += v * w.z; acc.w += v * w.w;
    }
    if (oq < 32) {
        float4 r;
        r.x = acc.x > 0.f ? 1.f + acc.x : expf(acc.x);
        r.y = acc.y > 0.f ? 1.f + acc.y : expf(acc.y);
        r.z = acc.z > 0.f ? 1.f + acc.z : expf(acc.z);
        r.w = acc.w > 0.f ? 1.f + acc.w : expf(acc.w);
        if (oq < 16) {
            *(float4*)&g_Q[node * HID + oq * 4] = r;
        } else {
            *(float4*)&g_Kf[node * HID + (oq - 16) * 4] = r;
            __half2* kh = (__half2*)&g_Kh[node * HID + (oq - 16) * 4];
            kh[0] = __floats2half2_rn(r.x, r.y);
            kh[1] = __floats2half2_rn(r.z, r.w);
        }
    } else {
        *(float4*)&g_V[node * NC + (oq - 32) * 4] = acc;
        __half2* vh = (__half2*)&g_Vh[node * NC + (oq - 32) * 4];
        vh[0] = __floats2half2_rn(acc.x, acc.y);
        vh[1] = __floats2half2_rn(acc.z, acc.w);
    }
}

// ---------------- teleport reduction ---------------------------------------
__global__ void k_tele() {
    __shared__ __align__(16) float sK[8 * HID];
    __shared__ __align__(16) float sV[8 * NC];
    int tid = threadIdx.x;  // 256
    float accM[8];
#pragma unroll
    for (int j = 0; j < 8; j++) accM[j] = 0.f;
    float accK = 0.f;
    for (int nb = blockIdx.x * 8; nb < NN; nb += gridDim.x * 8) {
        __syncthreads();
        for (int i = tid; i < 8 * HID; i += 256) {
            int n = i >> 6, f = i & 63;
            int node = nb + n;
            sK[i] = (node < NN) ? g_Kf[node * HID + f] : 0.f;
        }
        for (int i = tid; i < 8 * NC; i += 256) {
            int n = i >> 5, c = i & 31;
            int node = nb + n;
            sV[i] = (node < NN) ? g_V[node * NC + c] : 0.f;
        }
        __syncthreads();
#pragma unroll
        for (int j = 0; j < 8; j++) {
            int cell = j * 256 + tid;
            int ii = cell >> 5, cc = cell & 31;
            float a = 0.f;
#pragma unroll
            for (int n = 0; n < 8; n++) a += sK[n * HID + ii] * sV[n * NC + cc];
            accM[j] += a;
        }
        if (tid < HID) {
            float a = 0.f;
#pragma unroll
            for (int n = 0; n < 8; n++) a += sK[n * HID + tid];
            accK += a;
        }
    }
#pragma unroll
    for (int j = 0; j < 8; j++) atomicAdd(&g_tM[j * 256 + tid], accM[j]);
    if (tid < HID) atomicAdd(&g_tK[tid], accK);
}

// hidden init: hopwise[0]*V + teleport * (Q@tM/n) / (Q.tK/n + CST)
__global__ void k_init(const float* __restrict__ hopwise,
                       const float* __restrict__ teleport,
                       float* __restrict__ out) {
    __shared__ __align__(16) float sM[HID * NC];
    __shared__ float sKn[HID];
    int tid = threadIdx.x;
    const float inv_n = 1.0f / (float)NN;
    for (int i = tid; i < HID * NC; i += 256) sM[i] = g_tM[i] * inv_n;
    if (tid < HID) sKn[tid] = g_tK[tid] * inv_n;
    __syncthreads();
    int w = tid >> 5, lane = tid & 31;
    int j = blockIdx.x * 8 + w;
    if (j >= NN) return;
    float q0 = g_Q[j * HID + lane];
    float q1 = g_Q[j * HID + 32 + lane];
    float th = 0.f;
#pragma unroll
    for (int i = 0; i < 32; i++) th += __shfl_sync(FULL, q0, i) * sM[i * NC + lane];
#pragma unroll
    for (int i = 0; i < 32; i++) th += __shfl_sync(FULL, q1, i) * sM[(i + 32) * NC + lane];
    float p = q0 * sKn[lane] + q1 * sKn[32 + lane];
#pragma unroll
    for (int o = 16; o > 0; o >>= 1) p += __shfl_xor_sync(FULL, p, o);
    float tc = p + CSTF;
    out[j * NC + lane] = hopwise[0] * g_V[j * NC + lane] + teleport[0] * th / tc;
}

// ---------------- Kf propagation (fp16 rows) + coef ------------------------
__global__ void k_propK(int in_sel, int out_sel, const float* __restrict__ hopwise, int hop) {
    const __half* Kin = in_sel == 0 ? g_Kh : (in_sel == 1 ? g_Kha : g_Khb);
    __half* Kout = out_sel == 1 ? g_Kha : g_Khb;
    int w = threadIdx.x >> 5, lane = threadIdx.x & 31;
    int j = blockIdx.x * 8 + w;
    if (j >= NN) return;
    int r0 = g_cptr[j], r1 = g_cptr[j + 1];
    float2 acc = make_float2(0.f, 0.f);
    int off = 2 * lane;
    for (int base = r0; base < r1; base += 32) {
        int idx = base + lane;
        int s = 0; float ww = 0.f;
        if (idx < r1) {
            float2 sw = g_swp[idx];
            s = __float_as_int(sw.x); ww = sw.y;
        }
        int mm = min(32, r1 - base);
        int mmr = (mm + 3) & ~3;
        for (int i = 0; i < mmr; i += 4) {
            int s0 = __shfl_sync(FULL, s, i);
            int s1 = __shfl_sync(FULL, s, i + 1);
            int s2 = __shfl_sync(FULL, s, i + 2);
            int s3 = __shfl_sync(FULL, s, i + 3);
            float w0 = __shfl_sync(FULL, ww, i);
            float w1 = __shfl_sync(FULL, ww, i + 1);
            float w2 = __shfl_sync(FULL, ww, i + 2);
            float w3 = __shfl_sync(FULL, ww, i + 3);
            float2 k0 = __half22float2(*(const __half2*)&Kin[s0 * HID + off]);
            float2 k1 = __half22float2(*(const __half2*)&Kin[s1 * HID + off]);
            float2 k2 = __half22float2(*(const __half2*)&Kin[s2 * HID + off]);
            float2 k3 = __half22float2(*(const __half2*)&Kin[s3 * HID + off]);
            acc.x += w0 * k0.x; acc.y += w0 * k0.y;
            acc.x += w1 * k1.x; acc.y += w1 * k1.y;
            acc.x += w2 * k2.x; acc.y += w2 * k2.y;
            acc.x += w3 * k3.x; acc.y += w3 * k3.y;
        }
    }
    *(__half2*)&Kout[j * HID + off] = __floats2half2_rn(acc.x, acc.y);
    float2 q = *(const float2*)&g_Q[j * HID + off];
    float p = q.x * acc.x + q.y * acc.y;
#pragma unroll
    for (int o = 16; o > 0; o >>= 1) p += __shfl_xor_sync(FULL, p, o);
    if (lane == 0) g_coef[(hop - 1) * NN + j] = hopwise[hop] / (p + CSTF);
}

// ---------------- 16-wide epilogue: Q-contract + out accumulate -------------
// lane l holds 16 c-values for k = qoff + (l>>1), c = (l&1)*16 .. +16
__device__ __forceinline__ void epilogue16(float f[16], int j, int lane, int qoff,
                                           const float* coefh, float* out) {
    float qv = g_Q[j * HID + qoff + (lane >> 1)];
#pragma unroll
    for (int m = 0; m < 16; m++) f[m] *= qv;
#pragma unroll
    for (int mask = 2; mask <= 16; mask <<= 1) {
#pragma unroll
        for (int m = 0; m < 16; m++) f[m] += __shfl_xor_sync(FULL, f[m], mask);
    }
    if (lane < 2) {
        float cf = coefh[j];
        float4* o = (float4*)&out[j * NC + lane * 16];
#pragma unroll
        for (int v = 0; v < 4; v++) {
            float4 ov = o[v];
            ov.x += cf * f[v * 4 + 0]; ov.y += cf * f[v * 4 + 1];
            ov.z += cf * f[v * 4 + 2]; ov.w += cf * f[v * 4 + 3];
            o[v] = ov;
        }
    }
}

// quantize 16 floats to e4m3 with per-row scale (max -> 256); store row chunk
__device__ __forceinline__ void quant_store8(const float f[16], int j, int lane,
                                             uint4* __restrict__ Xout,
                                             float* __restrict__ sOut) {
    float m = 0.f;
#pragma unroll
    for (int t = 0; t < 16; t++) m = fmaxf(m, fabsf(f[t]));
#pragma unroll
    for (int o = 16; o > 0; o >>= 1) m = fmaxf(m, __shfl_xor_sync(FULL, m, o));
    float inv = (m > 0.f) ? __fdividef(256.f, m) : 0.f;
    unsigned wd[4];
#pragma unroll
    for (int t = 0; t < 4; t++) {
        float a0 = f[4 * t] * inv,     a1 = f[4 * t + 1] * inv;
        float a2 = f[4 * t + 2] * inv, a3 = f[4 * t + 3] * inv;
        unsigned short p01, p23;
        asm("cvt.rn.satfinite.e4m3x2.f32 %0, %1, %2;" : "=h"(p01) : "f"(a1), "f"(a0));
        asm("cvt.rn.satfinite.e4m3x2.f32 %0, %1, %2;" : "=h"(p23) : "f"(a3), "f"(a2));
        wd[t] = (unsigned)p01 | ((unsigned)p23 << 16);
    }
    Xout[j * 32 + lane] = make_uint4(wd[0], wd[1], wd[2], wd[3]);
    if (lane == 0) sOut[j] = m * (1.f / 256.f);
}

// fp8 gather accumulate: 16 e4m3 values, decode to half2, HFMA2 into acc[8]
__device__ __forceinline__ void acc16q(__half2 acc[8], uint4 x, __half2 wh) {
    const unsigned* px = (const unsigned*)&x;
#pragma unroll
    for (int t = 0; t < 4; t++) {
        __half2 a, b;
        asm("{\n\t"
            ".reg .b16 lo, hi;\n\t"
            "mov.b32 {lo, hi}, %2;\n\t"
            "cvt.rn.f16x2.e4m3x2 %0, lo;\n\t"
            "cvt.rn.f16x2.e4m3x2 %1, hi;\n\t"
            "}"
            : "=r"(*(unsigned*)&a), "=r"(*(unsigned*)&b) : "r"(px[t]));
        acc[2 * t]     = __hfma2(a, wh, acc[2 * t]);
        acc[2 * t + 1] = __hfma2(b, wh, acc[2 * t + 1]);
    }
}

__device__ __forceinline__ void acc16h(float f[16], uint4 a, uint4 b, float wv) {
    const unsigned* pa = (const unsigned*)&a;
    const unsigned* pb = (const unsigned*)&b;
#pragma unroll
    for (int t = 0; t < 4; t++) {
        float2 p = __half22float2(*(__half2*)&pa[t]);
        f[2 * t]     += wv * p.x;
        f[2 * t + 1] += wv * p.y;
    }
#pragma unroll
    for (int t = 0; t < 4; t++) {
        float2 p = __half22float2(*(__half2*)&pb[t]);
        f[8 + 2 * t]     += wv * p.x;
        f[8 + 2 * t + 1] += wv * p.y;
    }
}

// ---------------- hop 1: rank-1 fused gather (Kf ⊗ V) -> fp8 X1 (Xb) --------
__global__ void k_prop1(int qoff, float* __restrict__ out) {
    int w = threadIdx.x >> 5, lane = threadIdx.x & 31;
    int j = blockIdx.x * 8 + w;
    if (j >= NN) return;
    int r0 = g_cptr[j], r1 = g_cptr[j + 1];
    int kk = qoff + (lane >> 1);
    int c0 = (lane & 1) * 16;
    float f[16];
#pragma unroll
    for (int m = 0; m < 16; m++) f[m] = 0.f;
    for (int base = r0; base < r1; base += 32) {
        int idx = base + lane;
        int s = 0; float ww = 0.f;
        if (idx < r1) {
            float2 sw = g_swp[idx];
            s = __float_as_int(sw.x); ww = sw.y;
        }
        int mm = min(32, r1 - base);
        int mmr = (mm + 3) & ~3;
        for (int i = 0; i < mmr; i += 4) {
            int s0 = __shfl_sync(FULL, s, i);
            int s1 = __shfl_sync(FULL, s, i + 1);
            int s2 = __shfl_sync(FULL, s, i + 2);
            int s3 = __shfl_sync(FULL, s, i + 3);
            float w0 = __shfl_sync(FULL, ww, i);
            float w1 = __shfl_sync(FULL, ww, i + 1);
            float w2 = __shfl_sync(FULL, ww, i + 2);
            float w3 = __shfl_sync(FULL, ww, i + 3);
            const uint4* v0p = (const uint4*)&g_Vh[s0 * NC + c0];
            const uint4* v1p = (const uint4*)&g_Vh[s1 * NC + c0];
            const uint4* v2p = (const uint4*)&g_Vh[s2 * NC + c0];
            const uint4* v3p = (const uint4*)&g_Vh[s3 * NC + c0];
            uint4 a0 = v0p[0], b0 = v0p[1];
            uint4 a1 = v1p[0], b1 = v1p[1];
            uint4 a2 = v2p[0], b2 = v2p[1];
            uint4 a3 = v3p[0], b3 = v3p[1];
            float k0 = w0 * __half2float(g_Kh[s0 * HID + kk]);
            float k1 = w1 * __half2float(g_Kh[s1 * HID + kk]);
            float k2 = w2 * __half2float(g_Kh[s2 * HID + kk]);
            float k3 = w3 * __half2float(g_Kh[s3 * HID + kk]);
            acc16h(f, a0, b0, k0);
            acc16h(f, a1, b1, k1);
            acc16h(f, a2, b2, k2);
            acc16h(f, a3, b3, k3);
        }
    }
    quant_store8(f, j, lane, g_X8b, g_sB);
    epilogue16(f, j, lane, qoff, g_coef, out);
}

// ---------------- hops 2..4: fp8 X gather, half2 accumulate -----------------
__global__ void k_propM(int swap, int writeX, int hop, int qoff, float* __restrict__ out) {
    const uint4* Xin = swap ? g_X8b : g_X8a;
    uint4* Xout = swap ? g_X8a : g_X8b;
    const float* sIn = swap ? g_sB : g_sA;
    float* sOut = swap ? g_sA : g_sB;
    const float* coefh = g_coef + (hop - 1) * NN;
    int w = threadIdx.x >> 5, lane = threadIdx.x & 31;
    int j = blockIdx.x * 8 + w;
    if (j >= NN) return;
    int r0 = g_cptr[j], r1 = g_cptr[j + 1];
    __half2 acc[8];
#pragma unroll
    for (int m = 0; m < 8; m++) acc[m] = __floats2half2_rn(0.f, 0.f);
    for (int base = r0; base < r1; base += 32) {
        int idx = base + lane;
        int s = 0; float ww = 0.f;
        if (idx < r1) {
            float2 sw = g_swp[idx];
            s = __float_as_int(sw.x); ww = sw.y;
        }
        int mm = min(32, r1 - base);
        int mmr = (mm + 3) & ~3;
        for (int i = 0; i < mmr; i += 4) {
            int s0 = __shfl_sync(FULL, s, i);
            int s1 = __shfl_sync(FULL, s, i + 1);
            int s2 = __shfl_sync(FULL, s, i + 2);
            int s3 = __shfl_sync(FULL, s, i + 3);
            float w0 = __shfl_sync(FULL, ww, i);
            float w1 = __shfl_sync(FULL, ww, i + 1);
            float w2 = __shfl_sync(FULL, ww, i + 2);
            float w3 = __shfl_sync(FULL, ww, i + 3);
            uint4 x0 = Xin[s0 * 32 + lane];
            uint4 x1 = Xin[s1 * 32 + lane];
            uint4 x2 = Xin[s2 * 32 + lane];
            uint4 x3 = Xin[s3 * 32 + lane];
            __half2 c0 = __float2half2_rn(w0 * sIn[s0]);
            __half2 c1 = __float2half2_rn(w1 * sIn[s1]);
            __half2 c2 = __float2half2_rn(w2 * sIn[s2]);
            __half2 c3 = __float2half2_rn(w3 * sIn[s3]);
            acc16q(acc, x0, c0);
            acc16q(acc, x1, c1);
            acc16q(acc, x2, c2);
            acc16q(acc, x3, c3);
        }
    }
    float f[16];
#pragma unroll
    for (int m = 0; m < 8; m++) {
        float2 p = __half22float2(acc[m]);
        f[2 * m] = p.x;
        f[2 * m + 1] = p.y;
    }
    if (writeX) quant_store8(f, j, lane, Xout, sOut);
    epilogue16(f, j, lane, qoff, coefh, out);
}

// ---------------- launch ----------------------------------------------------
extern "C" void kernel_launch(void* const* d_in, const int* in_sizes, int n_in,
                              void* d_out, int out_size) {
    const float* nf       = (const float*)d_in[0];
    const float* W_in     = (const float*)d_in[1];
    const float* b_in     = (const float*)d_in[2];
    const float* WQ       = (const float*)d_in[3];
    const float* bQ       = (const float*)d_in[4];
    const float* WK       = (const float*)d_in[5];
    const float* bK       = (const float*)d_in[6];
    const float* WV       = (const float*)d_in[7];
    const float* bV       = (const float*)d_in[8];
    const float* hopwise  = (const float*)d_in[9];
    const float* teleport = (const float*)d_in[10];
    const int*   ei       = (const int*)d_in[11];
    const int* row = ei;
    const int* col = ei + EE;
    float* out = (float*)d_out;

    k_zero<<<(NN + 255) / 256, 256>>>();
    k_hist<<<EE / 256, 256>>>(col);
    k_dinv<<<(NN + 255) / 256, 256>>>();
    k_blksum<<<NBLK, 256>>>();
    k_scanblk<<<1, 256>>>();
    k_cptr<<<NBLK, 256>>>();
    k_scatter<<<EE / 256, 256>>>(row, col);
    k_gemmA<<<NN / 16, dim3(16, 16)>>>(nf, W_in, b_in);
    k_gemmB<<<NN / 8, dim3(40, 8)>>>(WQ, bQ, WK, bK, WV, bV);
    k_tele<<<200, 256>>>();
    k_init<<<NN / 8, 256>>>(hopwise, teleport, out);
    // Kf hops (fp16 rows): Kh -> Ka -> Kb -> Ka -> Kb; coef per hop
    k_propK<<<NN / 8, 256>>>(0, 1, hopwise, 1);
    k_propK<<<NN / 8, 256>>>(1, 2, hopwise, 2);
    k_propK<<<NN / 8, 256>>>(2, 1, hopwise, 3);
    k_propK<<<NN / 8, 256>>>(1, 2, hopwise, 4);
    // M propagation per 16-wide k-group; hop1 fused rank-1 -> fp8 X, hops 2-4 fp8
    for (int g = 0; g < NG; g++) {
        k_prop1<<<NN / 8, 256>>>(g * GK, out);          // -> X8b/sB (hop 1)
        k_propM<<<NN / 8, 256>>>(1, 1, 2, g * GK, out); // X8b -> X8a/sA
        k_propM<<<NN / 8, 256>>>(0, 1, 3, g * GK, out); // X8a -> X8b/sB
        k_propM<<<NN / 8, 256>>>(1, 0, 4, g * GK, out); // X8b (no write)
    }
}

// round 17
// speedup vs baseline: 1.3791x; 1.3791x over previous
#include <cuda_runtime.h>
#include <cuda_fp16.h>
#include <math.h>

#define NN 50000
#define EE 1600000
#define HID 64
#define NC 32
#define NFEAT 128
#define NG 8           // k-groups (64/8)
#define GK 8           // k-cols per group
#define RH 256         // halfs per X row = GK*NC
#define CSTF 1e-5f
#define FULL 0xffffffffu
#define NBLK ((NN + 255) / 256)

// ---------------- scratch (device globals; no allocation allowed) ----------
__device__ int    g_deg[NN];
__device__ float  g_dinv[NN];
__device__ int    g_cptr[NN + 1];
__device__ int    g_cnt[NN];
__device__ float2 g_swp[EE];      // packed (src-as-float-bits, wgt)
__device__ int    g_bsum[NBLK];
__device__ int    g_boff[NBLK];
__device__ float  g_x[NN * HID];
__device__ float  g_Q[NN * HID];
__device__ float  g_Kf[NN * HID];
__device__ float  g_V[NN * NC];
__device__ __half g_Kh[NN * HID];
__device__ __half g_Vh[NN * NC];
__device__ __half g_Kha[NN * HID];
__device__ __half g_Khb[NN * HID];
__device__ float  g_coef[4 * NN];
__device__ float  g_tM[HID * NC];
__device__ float  g_tK[HID];
// X buffers, c-major rows (half idx = c*GK + k'):
__device__ __half g_X1[(size_t)NG * NN * RH];  // full hop-1 result, 204.8 MB
__device__ __half g_Xa[NN * RH];               // 25.6 MB
__device__ __half g_Xb[NN * RH];               // 25.6 MB

// ---------------- setup kernels --------------------------------------------
__global__ void k_zero() {
    int i = blockIdx.x * blockDim.x + threadIdx.x;
    if (i < NN) { g_deg[i] = 0; g_cnt[i] = 0; }
    if (i < HID * NC) g_tM[i] = 0.f;
    if (i < HID) g_tK[i] = 0.f;
}

__global__ void k_hist(const int* __restrict__ col) {
    int e = blockIdx.x * blockDim.x + threadIdx.x;
    if (e < EE) atomicAdd(&g_deg[col[e]], 1);
}

__global__ void k_dinv() {
    int i = blockIdx.x * blockDim.x + threadIdx.x;
    if (i < NN) {
        int d = g_deg[i];
        g_dinv[i] = (d > 0) ? 1.0f / (float)d : 0.0f;
    }
}

__global__ void k_blksum() {
    __shared__ int sm[256];
    int b = blockIdx.x, t = threadIdx.x;
    int i = b * 256 + t;
    sm[t] = (i < NN) ? g_deg[i] : 0;
    __syncthreads();
    for (int o = 128; o > 0; o >>= 1) {
        if (t < o) sm[t] += sm[t + o];
        __syncthreads();
    }
    if (t == 0) g_bsum[b] = sm[0];
}

__global__ void k_scanblk() {
    __shared__ int sm[256];
    int t = threadIdx.x;
    int v = (t < NBLK) ? g_bsum[t] : 0;
    sm[t] = v;
    __syncthreads();
    for (int o = 1; o < 256; o <<= 1) {
        int u = 0;
        if (t >= o) u = sm[t - o];
        __syncthreads();
        sm[t] += u;
        __syncthreads();
    }
    if (t < NBLK) g_boff[t] = sm[t] - v;
}

__global__ void k_cptr() {
    __shared__ int sm[256];
    int b = blockIdx.x, t = threadIdx.x;
    int i = b * 256 + t;
    int v = (i < NN) ? g_deg[i] : 0;
    sm[t] = v;
    __syncthreads();
    for (int o = 1; o < 256; o <<= 1) {
        int u = 0;
        if (t >= o) u = sm[t - o];
        __syncthreads();
        sm[t] += u;
        __syncthreads();
    }
    int incl = sm[t];
    if (i < NN) g_cptr[i] = g_boff[b] + incl - v;
    if (i == NN - 1) g_cptr[NN] = g_boff[b] + incl;
}

__global__ void k_scatter(const int* __restrict__ row, const int* __restrict__ col) {
    int e = blockIdx.x * blockDim.x + threadIdx.x;
    if (e < EE) {
        int c = col[e];
        int r = row[e];
        int pos = g_cptr[c] + atomicAdd(&g_cnt[c], 1);
        g_swp[pos] = make_float2(__int_as_float(r), g_dinv[r]);
    }
}

// ---------------- input GEMMs ----------------------------------------------
__global__ void k_gemmA(const float* __restrict__ nf, const float* __restrict__ W,
                        const float* __restrict__ b) {
    __shared__ __align__(16) float Ws[NFEAT * HID];
    __shared__ __align__(16) float xs[16 * NFEAT];
    __shared__ __align__(16) float bs[HID];
    int tid = threadIdx.y * 16 + threadIdx.x;
    for (int i = tid; i < NFEAT * HID; i += 256) Ws[i] = W[i];
    if (tid < HID) bs[tid] = b[tid];
    int nb = blockIdx.x * 16;
    for (int i = tid; i < 16 * NFEAT; i += 256) {
        int n = i >> 7, f = i & 127;
        xs[i] = nf[(nb + n) * NFEAT + f];
    }
    __syncthreads();
    int node = nb + threadIdx.y;
    int oq = threadIdx.x;
    float4 acc = *(const float4*)&bs[oq * 4];
    const float* xr = &xs[threadIdx.y * NFEAT];
#pragma unroll 8
    for (int f = 0; f < NFEAT; f++) {
        float v = xr[f];
        float4 w = *(const float4*)&Ws[f * HID + oq * 4];
        acc.x += v * w.x; acc.y += v * w.y; acc.z += v * w.z; acc.w += v * w.w;
    }
    acc.x = fmaxf(acc.x, 0.f); acc.y = fmaxf(acc.y, 0.f);
    acc.z = fmaxf(acc.z, 0.f); acc.w = fmaxf(acc.w, 0.f);
    *(float4*)&g_x[node * HID + oq * 4] = acc;
}

__global__ void k_gemmB(const float* __restrict__ WQ, const float* __restrict__ bQ,
                        const float* __restrict__ WK, const float* __restrict__ bK,
                        const float* __restrict__ WV, const float* __restrict__ bV) {
    __shared__ __align__(16) float Wc[HID * 160];
    __shared__ __align__(16) float xs[8 * HID];
    __shared__ __align__(16) float bc[160];
    int tid = threadIdx.y * 40 + threadIdx.x;  // 320 threads
    for (int i = tid; i < HID * 160; i += 320) {
        int f = i / 160, o = i % 160;
        float v;
        if (o < 64) v = WQ[f * 64 + o];
        else if (o < 128) v = WK[f * 64 + (o - 64)];
        else v = WV[f * 32 + (o - 128)];
        Wc[i] = v;
    }
    if (tid < 160)
        bc[tid] = (tid < 64) ? bQ[tid] : ((tid < 128) ? bK[tid - 64] : bV[tid - 128]);
    int nb = blockIdx.x * 8;
    for (int i = tid; i < 8 * HID; i += 320) {
        int n = i >> 6, f = i & 63;
        xs[i] = g_x[(nb + n) * HID + f];
    }
    __syncthreads();
    int node = nb + threadIdx.y;
    int oq = threadIdx.x;
    float4 acc = *(const float4*)&bc[oq * 4];
    const float* xr = &xs[threadIdx.y * HID];
#pragma unroll 8
    for (int f = 0; f < HID; f++) {
        float v = xr[f];
        float4 w = *(const float4*)&Wc[f * 160 + oq * 4];
        acc.x += v * w.x; acc.y += v * w.y; acc.z += v * w.z; acc.w += v * w.w;
    }
    if (oq < 32) {
        float4 r;
        r.x = acc.x > 0.f ? 1.f + acc.x : expf(acc.x);
        r.y = acc.y > 0.f ? 1.f + acc.y : expf(acc.y);
        r.z = acc.z > 0.f ? 1.f + acc.z : expf(acc.z);
        r.w = acc.w > 0.f ? 1.f + acc.w : expf(acc.w);
        if (oq < 16) {
            *(float4*)&g_Q[node * HID + oq * 4] = r;
        } else {
            *(float4*)&g_Kf[node * HID + (oq - 16) * 4] = r;
            __half2* kh = (__half2*)&g_Kh[node * HID + (oq - 16) * 4];
            kh[0] = __floats2half2_rn(r.x, r.y);
            kh[1] = __floats2half2_rn(r.z, r.w);
        }
    } else {
        *(float4*)&g_V[node * NC + (oq - 32) * 4] = acc;
        __half2* vh = (__half2*)&g_Vh[node * NC + (oq - 32) * 4];
        vh[0] = __floats2half2_rn(acc.x, acc.y);
        vh[1] = __floats2half2_rn(acc.z, acc.w);
    }
}

// ---------------- teleport reduction ---------------------------------------
__global__ void k_tele() {
    __shared__ __align__(16) float sK[8 * HID];
    __shared__ __align__(16) float sV[8 * NC];
    int tid = threadIdx.x;  // 256
    float accM[8];
#pragma unroll
    for (int j = 0; j < 8; j++) accM[j] = 0.f;
    float accK = 0.f;
    for (int nb = blockIdx.x * 8; nb < NN; nb += gridDim.x * 8) {
        __syncthreads();
        for (int i = tid; i < 8 * HID; i += 256) {
            int n = i >> 6, f = i & 63;
            int node = nb + n;
            sK[i] = (node < NN) ? g_Kf[node * HID + f] : 0.f;
        }
        for (int i = tid; i < 8 * NC; i += 256) {
            int n = i >> 5, c = i & 31;
            int node = nb + n;
            sV[i] = (node < NN) ? g_V[node * NC + c] : 0.f;
        }
        __syncthreads();
#pragma unroll
        for (int j = 0; j < 8; j++) {
            int cell = j * 256 + tid;
            int ii = cell >> 5, cc = cell & 31;
            float a = 0.f;
#pragma unroll
            for (int n = 0; n < 8; n++) a += sK[n * HID + ii] * sV[n * NC + cc];
            accM[j] += a;
        }
        if (tid < HID) {
            float a = 0.f;
#pragma unroll
            for (int n = 0; n < 8; n++) a += sK[n * HID + tid];
            accK += a;
        }
    }
#pragma unroll
    for (int j = 0; j < 8; j++) atomicAdd(&g_tM[j * 256 + tid], accM[j]);
    if (tid < HID) atomicAdd(&g_tK[tid], accK);
}

// hidden init: hopwise[0]*V + teleport * (Q@tM/n) / (Q.tK/n + CST)
__global__ void k_init(const float* __restrict__ hopwise,
                       const float* __restrict__ teleport,
                       float* __restrict__ out) {
    __shared__ __align__(16) float sM[HID * NC];
    __shared__ float sKn[HID];
    int tid = threadIdx.x;
    const float inv_n = 1.0f / (float)NN;
    for (int i = tid; i < HID * NC; i += 256) sM[i] = g_tM[i] * inv_n;
    if (tid < HID) sKn[tid] = g_tK[tid] * inv_n;
    __syncthreads();
    int w = tid >> 5, lane = tid & 31;
    int j = blockIdx.x * 8 + w;
    if (j >= NN) return;
    float q0 = g_Q[j * HID + lane];
    float q1 = g_Q[j * HID + 32 + lane];
    float th = 0.f;
#pragma unroll
    for (int i = 0; i < 32; i++) th += __shfl_sync(FULL, q0, i) * sM[i * NC + lane];
#pragma unroll
    for (int i = 0; i < 32; i++) th += __shfl_sync(FULL, q1, i) * sM[(i + 32) * NC + lane];
    float p = q0 * sKn[lane] + q1 * sKn[32 + lane];
#pragma unroll
    for (int o = 16; o > 0; o >>= 1) p += __shfl_xor_sync(FULL, p, o);
    float tc = p + CSTF;
    out[j * NC + lane] = hopwise[0] * g_V[j * NC + lane] + teleport[0] * th / tc;
}

// ---------------- Kf propagation (fp16 rows) + coef ------------------------
__global__ void k_propK(int in_sel, int out_sel, const float* __restrict__ hopwise, int hop) {
    const __half* Kin = in_sel == 0 ? g_Kh : (in_sel == 1 ? g_Kha : g_Khb);
    __half* Kout = out_sel == 1 ? g_Kha : g_Khb;
    int w = threadIdx.x >> 5, lane = threadIdx.x & 31;
    int j = blockIdx.x * 8 + w;
    if (j >= NN) return;
    int r0 = g_cptr[j], r1 = g_cptr[j + 1];
    float2 acc = make_float2(0.f, 0.f);
    int off = 2 * lane;
    for (int base = r0; base < r1; base += 32) {
        int idx = base + lane;
        int s = 0; float ww = 0.f;
        if (idx < r1) {
            float2 sw = g_swp[idx];
            s = __float_as_int(sw.x); ww = sw.y;
        }
        int mm = min(32, r1 - base);
        int mmr = (mm + 3) & ~3;
        for (int i = 0; i < mmr; i += 4) {
            int s0 = __shfl_sync(FULL, s, i);
            int s1 = __shfl_sync(FULL, s, i + 1);
            int s2 = __shfl_sync(FULL, s, i + 2);
            int s3 = __shfl_sync(FULL, s, i + 3);
            float w0 = __shfl_sync(FULL, ww, i);
            float w1 = __shfl_sync(FULL, ww, i + 1);
            float w2 = __shfl_sync(FULL, ww, i + 2);
            float w3 = __shfl_sync(FULL, ww, i + 3);
            float2 k0 = __half22float2(*(const __half2*)&Kin[s0 * HID + off]);
            float2 k1 = __half22float2(*(const __half2*)&Kin[s1 * HID + off]);
            float2 k2 = __half22float2(*(const __half2*)&Kin[s2 * HID + off]);
            float2 k3 = __half22float2(*(const __half2*)&Kin[s3 * HID + off]);
            acc.x += w0 * k0.x; acc.y += w0 * k0.y;
            acc.x += w1 * k1.x; acc.y += w1 * k1.y;
            acc.x += w2 * k2.x; acc.y += w2 * k2.y;
            acc.x += w3 * k3.x; acc.y += w3 * k3.y;
        }
    }
    *(__half2*)&Kout[j * HID + off] = __floats2half2_rn(acc.x, acc.y);
    float2 q = *(const float2*)&g_Q[j * HID + off];
    float p = q.x * acc.x + q.y * acc.y;
#pragma unroll
    for (int o = 16; o > 0; o >>= 1) p += __shfl_xor_sync(FULL, p, o);
    if (lane == 0) g_coef[(hop - 1) * NN + j] = hopwise[hop] / (p + CSTF);
}

// ---------------- unified hop 1: one pass, full 64-k rank-1 gather ----------
// warp per target j; lane l owns c=l, all 64 k as 32 half2 (k-pairs).
// Writes X1 for all 8 groups (c-major rows) + hop-1 out contribution.
__global__ void k_hop1(float* __restrict__ out) {
    int w = threadIdx.x >> 5, lane = threadIdx.x & 31;
    int j = blockIdx.x * 8 + w;
    if (j >= NN) return;
    int r0 = g_cptr[j], r1 = g_cptr[j + 1];
    __half2 xa[32];
#pragma unroll
    for (int m = 0; m < 32; m++) xa[m] = __float2half2_rn(0.f);
    for (int base = r0; base < r1; base += 32) {
        int idx = base + lane;
        int s = 0; float ww = 0.f;
        if (idx < r1) {
            float2 sw = g_swp[idx];
            s = __float_as_int(sw.x); ww = sw.y;
        }
        int mm = min(32, r1 - base);
        for (int i = 0; i < mm; i++) {
            int ss = __shfl_sync(FULL, s, i);
            float wv = __shfl_sync(FULL, ww, i);
            __half vh = g_Vh[ss * NC + lane];                 // coalesced 64B row
            __half wh = __float2half_rn(wv);
            __half2 wv2 = __half2half2(__hmul(wh, vh));
            const uint4* kp = (const uint4*)&g_Kh[ss * HID];  // uniform 128B row
#pragma unroll
            for (int t = 0; t < 8; t++) {
                uint4 kq = kp[t];
                const __half2* k2 = (const __half2*)&kq;
                xa[4 * t + 0] = __hfma2(k2[0], wv2, xa[4 * t + 0]);
                xa[4 * t + 1] = __hfma2(k2[1], wv2, xa[4 * t + 1]);
                xa[4 * t + 2] = __hfma2(k2[2], wv2, xa[4 * t + 2]);
                xa[4 * t + 3] = __hfma2(k2[3], wv2, xa[4 * t + 3]);
            }
        }
    }
    // store X1 rows: group g row = c-major, lane writes its uint4 (k=8g..8g+8, c=lane)
#pragma unroll
    for (int g = 0; g < NG; g++) {
        *(uint4*)&g_X1[(size_t)g * NN * RH + (size_t)j * RH + lane * GK] =
            *(const uint4*)&xa[4 * g];
    }
    // hop-1 output: H[c=lane] = sum_k Q[k] * x[k,c]
    const float4* Qj = (const float4*)&g_Q[j * HID];
    float H = 0.f;
#pragma unroll
    for (int t = 0; t < 16; t++) {
        float4 q4 = Qj[t & 15];  // 16 float4 = 64 Q values
        // q4 covers k = 4t..4t+4 -> half2 pairs xa[2t], xa[2t+1]
        float2 p0 = __half22float2(xa[2 * t]);
        float2 p1 = __half22float2(xa[2 * t + 1]);
        H += q4.x * p0.x + q4.y * p0.y + q4.z * p1.x + q4.w * p1.y;
    }
    out[j * NC + lane] += g_coef[j] * H;
}

// ---------------- hops 2..4: fp16 X gather, c-major rows --------------------
__global__ void k_propM(int in_sel, int g, int writeX, int hop, float* __restrict__ out) {
    const __half* Xin = in_sel == 0 ? (g_X1 + (size_t)g * NN * RH)
                                    : (in_sel == 1 ? g_Xa : g_Xb);
    __half* Xout = (in_sel == 1) ? g_Xb : g_Xa;   // h2: X1->Xa, h3: Xa->Xb, h4: Xb (no write)
    const float* coefh = g_coef + (hop - 1) * NN;
    int w = threadIdx.x >> 5, lane = threadIdx.x & 31;
    int j = blockIdx.x * 8 + w;
    if (j >= NN) return;
    int r0 = g_cptr[j], r1 = g_cptr[j + 1];
    float f[8];
#pragma unroll
    for (int m = 0; m < 8; m++) f[m] = 0.f;
    for (int base = r0; base < r1; base += 32) {
        int idx = base + lane;
        int s = 0; float ww = 0.f;
        if (idx < r1) {
            float2 sw = g_swp[idx];
            s = __float_as_int(sw.x); ww = sw.y;
        }
        int mm = min(32, r1 - base);
        int mmr = (mm + 3) & ~3;
        for (int i = 0; i < mmr; i += 4) {
            int s0 = __shfl_sync(FULL, s, i);
            int s1 = __shfl_sync(FULL, s, i + 1);
            int s2 = __shfl_sync(FULL, s, i + 2);
            int s3 = __shfl_sync(FULL, s, i + 3);
            float w0 = __shfl_sync(FULL, ww, i);
            float w1 = __shfl_sync(FULL, ww, i + 1);
            float w2 = __shfl_sync(FULL, ww, i + 2);
            float w3 = __shfl_sync(FULL, ww, i + 3);
            uint4 x0 = *(const uint4*)&Xin[s0 * RH + lane * GK];
            uint4 x1 = *(const uint4*)&Xin[s1 * RH + lane * GK];
            uint4 x2 = *(const uint4*)&Xin[s2 * RH + lane * GK];
            uint4 x3 = *(const uint4*)&Xin[s3 * RH + lane * GK];
            const __half2* h0 = (const __half2*)&x0;
            const __half2* h1 = (const __half2*)&x1;
            const __half2* h2 = (const __half2*)&x2;
            const __half2* h3 = (const __half2*)&x3;
#pragma unroll
            for (int t = 0; t < 4; t++) {
                float2 p0 = __half22float2(h0[t]);
                float2 p1 = __half22float2(h1[t]);
                float2 p2 = __half22float2(h2[t]);
                float2 p3 = __half22float2(h3[t]);
                f[2 * t]     += w0 * p0.x + w1 * p1.x + w2 * p2.x + w3 * p3.x;
                f[2 * t + 1] += w0 * p0.y + w1 * p1.y + w2 * p2.y + w3 * p3.y;
            }
        }
    }
    if (writeX) {
        uint4 st;
        ((__half2*)&st)[0] = __floats2half2_rn(f[0], f[1]);
        ((__half2*)&st)[1] = __floats2half2_rn(f[2], f[3]);
        ((__half2*)&st)[2] = __floats2half2_rn(f[4], f[5]);
        ((__half2*)&st)[3] = __floats2half2_rn(f[6], f[7]);
        *(uint4*)&Xout[j * RH + lane * GK] = st;
    }
    // epilogue: H[c=lane] = sum_k' Q[g*8+k'] f[k']  (Q8 uniform per warp)
    const float4* Qj = (const float4*)&g_Q[j * HID + g * GK];
    float4 qa = Qj[0], qb = Qj[1];
    float H = qa.x * f[0] + qa.y * f[1] + qa.z * f[2] + qa.w * f[3]
            + qb.x * f[4] + qb.y * f[5] + qb.z * f[6] + qb.w * f[7];
    out[j * NC + lane] += coefh[j] * H;
}

// ---------------- launch ----------------------------------------------------
extern "C" void kernel_launch(void* const* d_in, const int* in_sizes, int n_in,
                              void* d_out, int out_size) {
    const float* nf       = (const float*)d_in[0];
    const float* W_in     = (const float*)d_in[1];
    const float* b_in     = (const float*)d_in[2];
    const float* WQ       = (const float*)d_in[3];
    const float* bQ       = (const float*)d_in[4];
    const float* WK       = (const float*)d_in[5];
    const float* bK       = (const float*)d_in[6];
    const float* WV       = (const float*)d_in[7];
    const float* bV       = (const float*)d_in[8];
    const float* hopwise  = (const float*)d_in[9];
    const float* teleport = (const float*)d_in[10];
    const int*   ei       = (const int*)d_in[11];
    const int* row = ei;
    const int* col = ei + EE;
    float* out = (float*)d_out;

    k_zero<<<(NN + 255) / 256, 256>>>();
    k_hist<<<EE / 256, 256>>>(col);
    k_dinv<<<(NN + 255) / 256, 256>>>();
    k_blksum<<<NBLK, 256>>>();
    k_scanblk<<<1, 256>>>();
    k_cptr<<<NBLK, 256>>>();
    k_scatter<<<EE / 256, 256>>>(row, col);
    k_gemmA<<<NN / 16, dim3(16, 16)>>>(nf, W_in, b_in);
    k_gemmB<<<NN / 8, dim3(40, 8)>>>(WQ, bQ, WK, bK, WV, bV);
    k_tele<<<200, 256>>>();
    k_init<<<NN / 8, 256>>>(hopwise, teleport, out);
    // Kf hops (fp16 rows): Kh -> Ka -> Kb -> Ka -> Kb; coef per hop
    k_propK<<<NN / 8, 256>>>(0, 1, hopwise, 1);
    k_propK<<<NN / 8, 256>>>(1, 2, hopwise, 2);
    k_propK<<<NN / 8, 256>>>(2, 1, hopwise, 3);
    k_propK<<<NN / 8, 256>>>(1, 2, hopwise, 4);
    // hop 1: single pass, writes all 8 group X1 buffers + out contribution
    k_hop1<<<NN / 8, 256>>>(out);
    // hops 2-4 per 8-wide k-group (c-major fp16 X)
    for (int g = 0; g < NG; g++) {
        k_propM<<<NN / 8, 256>>>(0, g, 1, 2, out);  // X1[g] -> Xa
        k_propM<<<NN / 8, 256>>>(1, g, 1, 3, out);  // Xa -> Xb
        k_propM<<<NN / 8, 256>>>(2, g, 0, 4, out);  // Xb (no write)
    }
}